// round 1
// baseline (speedup 1.0000x reference)
#include <cuda_runtime.h>
#include <math.h>
#include <stdint.h>

#define B 256
#define DIM 1024
#define H 8
#define D 128
#define P 2048
#define HD 1024
#define KER 4

// ---------------- scratch (static device memory; no allocs) ----------------
__device__ float g_xn[B * DIM];
__device__ float g_xt[B * P];
__device__ float g_xc[B * P];
__device__ float g_rt[B * HD];
__device__ float g_q[B * HD];
__device__ float g_k[B * HD];
__device__ float g_v[B * HD];
__device__ float g_o[B * HD];
__device__ float g_sk[B * HD];
__device__ float g_ie[B * H];
__device__ float g_fe[B * H];
__device__ float g_y[B * HD];

// ---------------- layernorm: one block per row of 1024 ----------------
__global__ void ln_kernel(const float* __restrict__ x, const float* __restrict__ g,
                          const float* __restrict__ bta, float* __restrict__ out) {
    int row = blockIdx.x;
    int tid = threadIdx.x;                     // 256 threads, 4 floats each
    const float4* xr = (const float4*)(x + (size_t)row * DIM);
    float4 v = xr[tid];
    float s  = v.x + v.y + v.z + v.w;
    float ss = v.x * v.x + v.y * v.y + v.z * v.z + v.w * v.w;
    __shared__ float shs[8], shss[8];
    __shared__ float mu_s, rstd_s;
    #pragma unroll
    for (int o = 16; o; o >>= 1) {
        s  += __shfl_down_sync(0xffffffffu, s, o);
        ss += __shfl_down_sync(0xffffffffu, ss, o);
    }
    int w = tid >> 5, lane = tid & 31;
    if (lane == 0) { shs[w] = s; shss[w] = ss; }
    __syncthreads();
    if (tid == 0) {
        float ts = 0.f, tss = 0.f;
        #pragma unroll
        for (int i = 0; i < 8; i++) { ts += shs[i]; tss += shss[i]; }
        float mu = ts * (1.f / DIM);
        float var = tss * (1.f / DIM) - mu * mu;
        mu_s = mu;
        rstd_s = rsqrtf(var + 1e-5f);
    }
    __syncthreads();
    float mu = mu_s, rs = rstd_s;
    float4 g4 = ((const float4*)g)[tid];
    float4 b4 = ((const float4*)bta)[tid];
    float4 r;
    r.x = (v.x - mu) * rs * g4.x + b4.x;
    r.y = (v.y - mu) * rs * g4.y + b4.y;
    r.z = (v.z - mu) * rs * g4.z + b4.z;
    r.w = (v.w - mu) * rs * g4.w + b4.w;
    ((float4*)(out + (size_t)row * DIM))[tid] = r;
}

// ---------------- sgemm NT: C[M,N] = A[M,K] @ W[N,K]^T + bias (+ epilogue) ----
struct GemmDesc {
    const float* A;
    const float* W;
    const float* bias;   // nullable
    const float* res;    // nullable residual added after epilogue
    float* C;
    int epi;             // 0 = none, 1 = sigmoid
};
struct GemmArgs {
    GemmDesc d[5];
    int N;
    int K;
};

#define BM 64
#define BN 64
#define BK 32

__global__ __launch_bounds__(256, 2) void gemm_nt(GemmArgs args) {
    const GemmDesc dd = args.d[blockIdx.z];
    const int N = args.N, K = args.K;
    const float* __restrict__ A = dd.A;
    const float* __restrict__ W = dd.W;
    __shared__ float As[BK][BM];
    __shared__ float Bs[BK][BN];
    int tid = threadIdx.x;
    int bm0 = blockIdx.y * BM, bn0 = blockIdx.x * BN;
    int ty = tid >> 4, tx = tid & 15;          // 16x16 thread grid, 4x4 tile each
    float acc[4][4] = {};

    for (int k0 = 0; k0 < K; k0 += BK) {
        #pragma unroll
        for (int i = 0; i < 2; i++) {
            int f = tid + i * 256;             // 0..511 float4 slots per tile
            int m = f >> 3, kq = f & 7;
            float4 a = *(const float4*)(A + (size_t)(bm0 + m) * K + k0 + kq * 4);
            As[kq * 4 + 0][m] = a.x; As[kq * 4 + 1][m] = a.y;
            As[kq * 4 + 2][m] = a.z; As[kq * 4 + 3][m] = a.w;
            float4 b = *(const float4*)(W + (size_t)(bn0 + m) * K + k0 + kq * 4);
            Bs[kq * 4 + 0][m] = b.x; Bs[kq * 4 + 1][m] = b.y;
            Bs[kq * 4 + 2][m] = b.z; Bs[kq * 4 + 3][m] = b.w;
        }
        __syncthreads();
        #pragma unroll
        for (int kk = 0; kk < BK; kk++) {
            float4 am = *(const float4*)&As[kk][ty * 4];
            float4 bn = *(const float4*)&Bs[kk][tx * 4];
            float rm[4] = {am.x, am.y, am.z, am.w};
            float rn[4] = {bn.x, bn.y, bn.z, bn.w};
            #pragma unroll
            for (int i = 0; i < 4; i++)
                #pragma unroll
                for (int j = 0; j < 4; j++) acc[i][j] += rm[i] * rn[j];
        }
        __syncthreads();
    }

    float bias[4];
    if (dd.bias) {
        float4 bb = *(const float4*)(dd.bias + bn0 + tx * 4);
        bias[0] = bb.x; bias[1] = bb.y; bias[2] = bb.z; bias[3] = bb.w;
    } else {
        bias[0] = bias[1] = bias[2] = bias[3] = 0.f;
    }
    #pragma unroll
    for (int i = 0; i < 4; i++) {
        int row = bm0 + ty * 4 + i;
        float vals[4];
        #pragma unroll
        for (int j = 0; j < 4; j++) {
            float t = acc[i][j] + bias[j];
            if (dd.epi == 1) t = 1.f / (1.f + expf(-t));
            if (dd.res) t += dd.res[(size_t)row * N + bn0 + tx * 4 + j];
            vals[j] = t;
        }
        *(float4*)(dd.C + (size_t)row * N + bn0 + tx * 4) =
            make_float4(vals[0], vals[1], vals[2], vals[3]);
    }
}

// ---------------- causal conv (k=4) along feature axis + silu ----------------
__global__ void conv_silu_kernel(const float* __restrict__ xt, const float* __restrict__ w,
                                 const float* __restrict__ cb, float* __restrict__ xc) {
    int b = blockIdx.y;
    int p = blockIdx.x * 256 + threadIdx.x;
    const float* xr = xt + (size_t)b * P;
    float acc = cb[0];
    #pragma unroll
    for (int j = 0; j < KER; j++) {
        int idx = p - (KER - 1) + j;
        if (idx >= 0) acc += w[j] * xr[idx];
    }
    float s = 1.f / (1.f + expf(-acc));
    xc[(size_t)b * P + p] = acc * s;
}

// ---------------- i/f gates + m_t + exp factors (8 heads, K=2048) -----------
__global__ void if_kernel(const float* __restrict__ xc,
                          const float* __restrict__ Wi, const float* __restrict__ bi,
                          const float* __restrict__ Wf, const float* __restrict__ bf,
                          const float* __restrict__ m_tm1, float* __restrict__ m_out,
                          float* __restrict__ ie, float* __restrict__ fe) {
    int b = blockIdx.x;
    int w = threadIdx.x >> 5, lane = threadIdx.x & 31;   // 8 warps = 8 heads
    const float* x  = xc + (size_t)b * P;
    const float* wi = Wi + (size_t)w * P;
    const float* wf = Wf + (size_t)w * P;
    float ai = 0.f, af = 0.f;
    for (int k = lane * 4; k < P; k += 128) {
        float4 xv  = *(const float4*)(x + k);
        float4 wiv = *(const float4*)(wi + k);
        float4 wfv = *(const float4*)(wf + k);
        ai += xv.x * wiv.x + xv.y * wiv.y + xv.z * wiv.z + xv.w * wiv.w;
        af += xv.x * wfv.x + xv.y * wfv.y + xv.z * wfv.z + xv.w * wfv.w;
    }
    #pragma unroll
    for (int o = 16; o; o >>= 1) {
        ai += __shfl_down_sync(0xffffffffu, ai, o);
        af += __shfl_down_sync(0xffffffffu, af, o);
    }
    if (lane == 0) {
        float i_t = ai + bi[w];
        float f_t = af + bf[w];
        float mp = m_tm1[b * H + w];
        float m = fmaxf(f_t + mp, i_t);
        m_out[b * H + w] = m;
        ie[b * H + w] = expf(i_t - m);
        fe[b * H + w] = expf(f_t - m + mp);
    }
}

// ---------------- fused state update + readout + groupnorm + gating ---------
// one block per (b,h); 128 threads; one pass over the 128x128 c tile
__global__ __launch_bounds__(128) void state_kernel(
    const float* __restrict__ c_tm1, const float* __restrict__ n_tm1,
    const float* __restrict__ q, const float* __restrict__ k, const float* __restrict__ v,
    const float* __restrict__ o, const float* __restrict__ ie_, const float* __restrict__ fe_,
    const float* __restrict__ skip, const float* __restrict__ r,
    const float* __restrict__ gn_g, const float* __restrict__ gn_b,
    float* __restrict__ c_out, float* __restrict__ n_out, float* __restrict__ y) {
    int bh = blockIdx.x;
    int b = bh >> 3, h = bh & 7;
    __shared__ float qs[D], ks[D], vs[D], hnum[D];
    __shared__ float red[4], rs1[4], rs2[4];
    int tid = threadIdx.x;
    int base = b * HD + h * D;
    qs[tid] = q[base + tid];
    ks[tid] = k[base + tid] * 0.08838834764831845f;   // 1/sqrt(128)
    vs[tid] = v[base + tid];
    float ie = ie_[bh], fe = fe_[bh];
    __syncthreads();

    const float4* crow = (const float4*)(c_tm1 + (size_t)bh * D * D);
    float4* cout = (float4*)(c_out + (size_t)bh * D * D);
    int w = tid >> 5, lane = tid & 31;
    float4 k4 = ((const float4*)ks)[lane];
    float4 q4 = ((const float4*)qs)[lane];
    #pragma unroll 4
    for (int it = 0; it < 32; it++) {
        int d = it * 4 + w;
        float4 c4 = crow[d * 32 + lane];
        float ivd = ie * vs[d];
        float4 cn;
        cn.x = fe * c4.x + ivd * k4.x;
        cn.y = fe * c4.y + ivd * k4.y;
        cn.z = fe * c4.z + ivd * k4.z;
        cn.w = fe * c4.w + ivd * k4.w;
        cout[d * 32 + lane] = cn;
        float part = cn.x * q4.x + cn.y * q4.y + cn.z * q4.z + cn.w * q4.w;
        #pragma unroll
        for (int off = 16; off; off >>= 1) part += __shfl_down_sync(0xffffffffu, part, off);
        if (lane == 0) hnum[d] = part;
    }
    __syncthreads();

    int d = tid;
    float nv = fe * n_tm1[bh * D + d] + ie * ks[d];
    n_out[bh * D + d] = nv;
    float dn = nv * qs[d];
    #pragma unroll
    for (int off = 16; off; off >>= 1) dn += __shfl_down_sync(0xffffffffu, dn, off);
    if (lane == 0) red[w] = dn;
    __syncthreads();
    float denom = fmaxf(red[0] + red[1] + red[2] + red[3], 1.0f);
    float ht = o[base + d] * hnum[d] / denom;

    float s1 = ht, s2 = ht * ht;
    #pragma unroll
    for (int off = 16; off; off >>= 1) {
        s1 += __shfl_down_sync(0xffffffffu, s1, off);
        s2 += __shfl_down_sync(0xffffffffu, s2, off);
    }
    if (lane == 0) { rs1[w] = s1; rs2[w] = s2; }
    __syncthreads();
    float mu  = (rs1[0] + rs1[1] + rs1[2] + rs1[3]) * (1.f / D);
    float var = (rs2[0] + rs2[1] + rs2[2] + rs2[3]) * (1.f / D) - mu * mu;
    float rstd = rsqrtf(var + 1e-5f);
    float xn = (ht - mu) * rstd * gn_g[h * D + d] + gn_b[h * D + d];
    float rv = r[base + d];
    float yv = (xn + skip[base + d]) * (rv / (1.f + expf(-rv)));
    y[base + d] = yv;
}

// ---------------------------------------------------------------------------
extern "C" void kernel_launch(void* const* d_in, const int* in_sizes, int n_in,
                              void* d_out, int out_size) {
    const float* seq    = (const float*)d_in[0];
    const float* c_tm1  = (const float*)d_in[1];
    const float* n_tm1  = (const float*)d_in[2];
    const float* m_tm1  = (const float*)d_in[3];
    const float* ln_g   = (const float*)d_in[4];
    const float* ln_b   = (const float*)d_in[5];
    const float* Wul    = (const float*)d_in[6];
    const float* bul    = (const float*)d_in[7];
    const float* Wur    = (const float*)d_in[8];
    const float* bur    = (const float*)d_in[9];
    const float* conv_w = (const float*)d_in[10];
    const float* conv_b = (const float*)d_in[11];
    const float* Wskip  = (const float*)d_in[12];
    const float* Wi     = (const float*)d_in[13];
    const float* bi     = (const float*)d_in[14];
    const float* Wf     = (const float*)d_in[15];
    const float* bf     = (const float*)d_in[16];
    const float* Wo     = (const float*)d_in[17];
    const float* bo     = (const float*)d_in[18];
    const float* Wq     = (const float*)d_in[19];
    const float* bq     = (const float*)d_in[20];
    const float* Wk     = (const float*)d_in[21];
    const float* bk     = (const float*)d_in[22];
    const float* Wv     = (const float*)d_in[23];
    const float* bv     = (const float*)d_in[24];
    const float* gn_g   = (const float*)d_in[25];
    const float* gn_b   = (const float*)d_in[26];
    const float* Wd     = (const float*)d_in[27];
    const float* bd     = (const float*)d_in[28];

    float* out   = (float*)d_out;                       // [B, DIM]
    float* c_out = out + (size_t)B * DIM;               // [B,H,D,D]
    float* n_out = c_out + (size_t)B * H * D * D;       // [B,H,D]
    float* m_out = n_out + (size_t)B * H * D;           // [B,H]

    float *xn, *xt, *xc, *rt, *qq, *kk, *vv, *oo, *sk, *iee, *fee, *yy;
    cudaGetSymbolAddress((void**)&xn,  g_xn);
    cudaGetSymbolAddress((void**)&xt,  g_xt);
    cudaGetSymbolAddress((void**)&xc,  g_xc);
    cudaGetSymbolAddress((void**)&rt,  g_rt);
    cudaGetSymbolAddress((void**)&qq,  g_q);
    cudaGetSymbolAddress((void**)&kk,  g_k);
    cudaGetSymbolAddress((void**)&vv,  g_v);
    cudaGetSymbolAddress((void**)&oo,  g_o);
    cudaGetSymbolAddress((void**)&sk,  g_sk);
    cudaGetSymbolAddress((void**)&iee, g_ie);
    cudaGetSymbolAddress((void**)&fee, g_fe);
    cudaGetSymbolAddress((void**)&yy,  g_y);

    // 1. layernorm
    ln_kernel<<<B, 256>>>(seq, ln_g, ln_b, xn);

    // 2. x_t = x_n @ Wul^T + bul   [B, P]
    {
        GemmArgs a{}; a.N = P; a.K = DIM;
        a.d[0] = {xn, Wul, bul, nullptr, xt, 0};
        gemm_nt<<<dim3(P / BN, B / BM, 1), 256>>>(a);
    }
    // 3. r_t = x_n @ Wur^T + bur   [B, HD]
    {
        GemmArgs a{}; a.N = HD; a.K = DIM;
        a.d[0] = {xn, Wur, bur, nullptr, rt, 0};
        gemm_nt<<<dim3(HD / BN, B / BM, 1), 256>>>(a);
    }
    // 4. causal conv + silu -> x_c
    conv_silu_kernel<<<dim3(P / 256, B), 256>>>(xt, conv_w, conv_b, xc);

    // 5. gates i,f + m_t + exp factors
    if_kernel<<<B, 256>>>(xc, Wi, bi, Wf, bf, m_tm1, m_out, iee, fee);

    // 6. batched 5x GEMM (N=1024, K=2048): q,k from x_c; v,o from x_t; skip from x_c
    {
        GemmArgs a{}; a.N = HD; a.K = P;
        a.d[0] = {xc, Wq,    bq,      nullptr, qq, 0};
        a.d[1] = {xc, Wk,    bk,      nullptr, kk, 0};
        a.d[2] = {xt, Wv,    bv,      nullptr, vv, 0};
        a.d[3] = {xt, Wo,    bo,      nullptr, oo, 1};   // sigmoid
        a.d[4] = {xc, Wskip, nullptr, nullptr, sk, 0};
        gemm_nt<<<dim3(HD / BN, B / BM, 5), 256>>>(a);
    }

    // 7. fused state update + readout + groupnorm + skip + silu(r) gate
    state_kernel<<<B * H, 128>>>(c_tm1, n_tm1, qq, kk, vv, oo, iee, fee,
                                 sk, rt, gn_g, gn_b, c_out, n_out, yy);

    // 8. out = y @ Wd^T + bd + seq
    {
        GemmArgs a{}; a.N = DIM; a.K = HD;
        a.d[0] = {yy, Wd, bd, seq, out, 0};
        gemm_nt<<<dim3(DIM / BN, B / BM, 1), 256>>>(a);
    }
}

// round 3
// speedup vs baseline: 2.2749x; 2.2749x over previous
#include <cuda_runtime.h>
#include <cuda_bf16.h>
#include <math.h>
#include <stdint.h>

#define B 256
#define DIM 1024
#define H 8
#define D 128
#define P 2048
#define HD 1024
#define KER 4

// ---------------- scratch (static device memory; no allocs) ----------------
__device__ float g_xn[B * DIM];
__device__ float g_xt[B * P];
__device__ float g_xc[B * P];
__device__ float g_rt[B * HD];
__device__ float g_q[B * HD];
__device__ float g_k[B * HD];
__device__ float g_v[B * HD];
__device__ float g_o[B * HD];
__device__ float g_sk[B * HD];
__device__ float g_ie[B * H];
__device__ float g_fe[B * H];
__device__ float g_y[B * HD];

__device__ __forceinline__ uint32_t smem_u32(const void* p) {
    uint32_t a;
    asm("{ .reg .u64 t; cvta.to.shared.u64 t, %1; cvt.u32.u64 %0, t; }" : "=r"(a) : "l"(p));
    return a;
}

#define LDM4(r, a) \
    asm volatile("ldmatrix.sync.aligned.m8n8.x4.shared.b16 {%0,%1,%2,%3}, [%4];" \
        : "=r"((r)[0]), "=r"((r)[1]), "=r"((r)[2]), "=r"((r)[3]) : "r"(a))

#define MMA(d, a, b0, b1) \
    asm volatile("mma.sync.aligned.m16n8k16.row.col.f32.bf16.bf16.f32 " \
        "{%0,%1,%2,%3}, {%4,%5,%6,%7}, {%8,%9}, {%0,%1,%2,%3};" \
        : "+f"((d)[0]), "+f"((d)[1]), "+f"((d)[2]), "+f"((d)[3]) \
        : "r"((a)[0]), "r"((a)[1]), "r"((a)[2]), "r"((a)[3]), "r"(b0), "r"(b1))

// ================= layernorm =================
__global__ void ln_kernel(const float* __restrict__ x, const float* __restrict__ g,
                          const float* __restrict__ bta, float* __restrict__ out) {
    int row = blockIdx.x;
    int tid = threadIdx.x;
    const float4* xr = (const float4*)(x + (size_t)row * DIM);
    float4 v = xr[tid];
    float s  = v.x + v.y + v.z + v.w;
    float ss = v.x * v.x + v.y * v.y + v.z * v.z + v.w * v.w;
    __shared__ float shs[8], shss[8];
    __shared__ float mu_s, rstd_s;
    #pragma unroll
    for (int o = 16; o; o >>= 1) {
        s  += __shfl_down_sync(0xffffffffu, s, o);
        ss += __shfl_down_sync(0xffffffffu, ss, o);
    }
    int w = tid >> 5, lane = tid & 31;
    if (lane == 0) { shs[w] = s; shss[w] = ss; }
    __syncthreads();
    if (tid == 0) {
        float ts = 0.f, tss = 0.f;
        #pragma unroll
        for (int i = 0; i < 8; i++) { ts += shs[i]; tss += shss[i]; }
        float mu = ts * (1.f / DIM);
        float var = tss * (1.f / DIM) - mu * mu;
        mu_s = mu;
        rstd_s = rsqrtf(var + 1e-5f);
    }
    __syncthreads();
    float mu = mu_s, rs = rstd_s;
    float4 g4 = ((const float4*)g)[tid];
    float4 b4 = ((const float4*)bta)[tid];
    float4 r;
    r.x = (v.x - mu) * rs * g4.x + b4.x;
    r.y = (v.y - mu) * rs * g4.y + b4.y;
    r.z = (v.z - mu) * rs * g4.z + b4.z;
    r.w = (v.w - mu) * rs * g4.w + b4.w;
    ((float4*)(out + (size_t)row * DIM))[tid] = r;
}

// ================= tensor-core GEMM NT via mma.sync ==================
// C[M,N] = A[M,K] @ W[N,K]^T, fp32 in/out, bf16 hi/lo split (3 MMA terms)
struct GemmDesc {
    const float* A;
    const float* W;
    const float* bias;   // nullable
    const float* res;    // nullable
    float* C;
    int N;
    int K;
    int epi;             // 0 none, 1 sigmoid
};
struct GemmArgs { GemmDesc d[5]; };

#define TILE 128
#define LDT 40                     // padded row stride in halves (80 bytes)
#define MAT_BYTES (128 * LDT * 2)  // 10240 bytes per bf16 matrix
#define STAGE (4 * MAT_BYTES)      // A_hi A_lo W_hi W_lo
#define GEMM_SMEM (2 * STAGE)      // 81920

// global -> regs (4 float4 per thread; tile 128 rows x 32 cols fp32)
__device__ __forceinline__ void ldg_tile(const float* __restrict__ g, int row0, int K,
                                         int k0, float4 (&p)[4], int tid) {
    #pragma unroll
    for (int i = 0; i < 4; i++) {
        int idx = tid + i * 256;
        int r = idx >> 3, kq = idx & 7;
        p[i] = *(const float4*)(g + (size_t)(row0 + r) * K + k0 + (kq << 2));
    }
}
// regs -> bf16 hi/lo -> padded SMEM
__device__ __forceinline__ void cvt_sts(const float4 (&p)[4], char* hi, char* lo, int tid) {
    #pragma unroll
    for (int i = 0; i < 4; i++) {
        int idx = tid + i * 256;
        int r = idx >> 3, kq = idx & 7;
        float4 v = p[i];
        uint32_t u0 = __float_as_uint(v.x), u1 = __float_as_uint(v.y);
        uint32_t u2 = __float_as_uint(v.z), u3 = __float_as_uint(v.w);
        uint32_t h01 = __byte_perm(u0, u1, 0x7632);
        uint32_t h23 = __byte_perm(u2, u3, 0x7632);
        float r0 = v.x - __uint_as_float(u0 & 0xffff0000u);
        float r1 = v.y - __uint_as_float(u1 & 0xffff0000u);
        float r2 = v.z - __uint_as_float(u2 & 0xffff0000u);
        float r3 = v.w - __uint_as_float(u3 & 0xffff0000u);
        uint32_t l01, l23;
        asm("cvt.rn.bf16x2.f32 %0, %1, %2;" : "=r"(l01) : "f"(r1), "f"(r0));
        asm("cvt.rn.bf16x2.f32 %0, %1, %2;" : "=r"(l23) : "f"(r3), "f"(r2));
        int off = r * (LDT * 2) + kq * 8;
        *(uint2*)(hi + off) = make_uint2(h01, h23);
        *(uint2*)(lo + off) = make_uint2(l01, l23);
    }
}

__global__ __launch_bounds__(256, 1) void gemm_mma(GemmArgs args) {
    extern __shared__ char smem[];
    const GemmDesc dd = args.d[blockIdx.z];
    const int N = dd.N, K = dd.K;
    const int bn0 = blockIdx.x * TILE;
    const int bm0 = blockIdx.y * TILE;
    if (bn0 >= N) return;

    const int tid = threadIdx.x;
    const int wid = tid >> 5, lane = tid & 31;
    const int m0 = (wid & 1) * 64;        // warp M offset in tile
    const int n0 = (wid >> 1) * 32;       // warp N offset in tile
    const int grp = lane >> 3, lrow = lane & 7;
    const uint32_t sbase = smem_u32(smem);

    // ldmatrix lane address offsets (bytes within a bf16 matrix)
    uint32_t aoff[4], boff[2];
    #pragma unroll
    for (int mi = 0; mi < 4; mi++)
        aoff[mi] = (uint32_t)((m0 + mi * 16 + (grp & 1) * 8 + lrow) * (LDT * 2) + (grp >> 1) * 16);
    #pragma unroll
    for (int bi = 0; bi < 2; bi++)
        boff[bi] = (uint32_t)((n0 + bi * 16 + (grp >> 1) * 8 + lrow) * (LDT * 2) + (grp & 1) * 16);

    float acc[4][4][4];
    #pragma unroll
    for (int mi = 0; mi < 4; mi++)
        #pragma unroll
        for (int ni = 0; ni < 4; ni++)
            acc[mi][ni][0] = acc[mi][ni][1] = acc[mi][ni][2] = acc[mi][ni][3] = 0.f;

    const int nk = K >> 5;
    // prologue: fill stage 0
    {
        float4 pA[4], pW[4];
        ldg_tile(dd.A, bm0, K, 0, pA, tid);
        ldg_tile(dd.W, bn0, K, 0, pW, tid);
        cvt_sts(pA, smem, smem + MAT_BYTES, tid);
        cvt_sts(pW, smem + 2 * MAT_BYTES, smem + 3 * MAT_BYTES, tid);
    }
    __syncthreads();

    for (int it = 0; it < nk; it++) {
        float4 pA[4], pW[4];
        if (it + 1 < nk) {
            ldg_tile(dd.A, bm0, K, (it + 1) << 5, pA, tid);
            ldg_tile(dd.W, bn0, K, (it + 1) << 5, pW, tid);
        }
        const uint32_t sA = sbase + (it & 1) * STAGE;
        const uint32_t sW = sA + 2 * MAT_BYTES;
        #pragma unroll
        for (int ks = 0; ks < 2; ks++) {
            const uint32_t kb = ks * 32;   // 16 halves
            uint32_t Ah[4][4], Al[4][4], Bh[4][2], Bl[4][2];
            #pragma unroll
            for (int mi = 0; mi < 4; mi++) {
                LDM4(Ah[mi], sA + aoff[mi] + kb);
                LDM4(Al[mi], sA + MAT_BYTES + aoff[mi] + kb);
            }
            #pragma unroll
            for (int bi = 0; bi < 2; bi++) {
                uint32_t t[4];
                LDM4(t, sW + boff[bi] + kb);
                Bh[2 * bi][0] = t[0]; Bh[2 * bi][1] = t[1];
                Bh[2 * bi + 1][0] = t[2]; Bh[2 * bi + 1][1] = t[3];
                LDM4(t, sW + MAT_BYTES + boff[bi] + kb);
                Bl[2 * bi][0] = t[0]; Bl[2 * bi][1] = t[1];
                Bl[2 * bi + 1][0] = t[2]; Bl[2 * bi + 1][1] = t[3];
            }
            #pragma unroll
            for (int mi = 0; mi < 4; mi++)
                #pragma unroll
                for (int ni = 0; ni < 4; ni++) {
                    MMA(acc[mi][ni], Ah[mi], Bh[ni][0], Bh[ni][1]);
                    MMA(acc[mi][ni], Ah[mi], Bl[ni][0], Bl[ni][1]);
                    MMA(acc[mi][ni], Al[mi], Bh[ni][0], Bh[ni][1]);
                }
        }
        if (it + 1 < nk) {
            char* st = smem + ((it + 1) & 1) * STAGE;
            cvt_sts(pA, st, st + MAT_BYTES, tid);
            cvt_sts(pW, st + 2 * MAT_BYTES, st + 3 * MAT_BYTES, tid);
        }
        __syncthreads();
    }

    // epilogue: direct stores (float2 per fragment half)
    const int qrow = lane >> 2, qcol = (lane & 3) * 2;
    #pragma unroll
    for (int ni = 0; ni < 4; ni++) {
        const int c = bn0 + n0 + ni * 8 + qcol;
        float2 bb = make_float2(0.f, 0.f);
        if (dd.bias) bb = *(const float2*)(dd.bias + c);
        #pragma unroll
        for (int mi = 0; mi < 4; mi++) {
            const int r = bm0 + m0 + mi * 16 + qrow;
            float v0 = acc[mi][ni][0] + bb.x;
            float v1 = acc[mi][ni][1] + bb.y;
            float v2 = acc[mi][ni][2] + bb.x;
            float v3 = acc[mi][ni][3] + bb.y;
            if (dd.epi == 1) {
                v0 = 1.f / (1.f + expf(-v0)); v1 = 1.f / (1.f + expf(-v1));
                v2 = 1.f / (1.f + expf(-v2)); v3 = 1.f / (1.f + expf(-v3));
            }
            if (dd.res) {
                float2 r0 = *(const float2*)(dd.res + (size_t)r * N + c);
                float2 r1 = *(const float2*)(dd.res + (size_t)(r + 8) * N + c);
                v0 += r0.x; v1 += r0.y; v2 += r1.x; v3 += r1.y;
            }
            *(float2*)(dd.C + (size_t)r * N + c) = make_float2(v0, v1);
            *(float2*)(dd.C + (size_t)(r + 8) * N + c) = make_float2(v2, v3);
        }
    }
}

// ================= causal conv (k=4) + silu =================
__global__ void conv_silu_kernel(const float* __restrict__ xt, const float* __restrict__ w,
                                 const float* __restrict__ cb, float* __restrict__ xc) {
    int b = blockIdx.y;
    int p = blockIdx.x * 256 + threadIdx.x;
    const float* xr = xt + (size_t)b * P;
    float acc = cb[0];
    #pragma unroll
    for (int j = 0; j < KER; j++) {
        int idx = p - (KER - 1) + j;
        if (idx >= 0) acc += w[j] * xr[idx];
    }
    float s = 1.f / (1.f + expf(-acc));
    xc[(size_t)b * P + p] = acc * s;
}

// ================= i/f gates + m_t + exp factors =================
__global__ void if_kernel(const float* __restrict__ xc,
                          const float* __restrict__ Wi, const float* __restrict__ bi,
                          const float* __restrict__ Wf, const float* __restrict__ bf,
                          const float* __restrict__ m_tm1, float* __restrict__ m_out,
                          float* __restrict__ ie, float* __restrict__ fe) {
    int b = blockIdx.x;
    int w = threadIdx.x >> 5, lane = threadIdx.x & 31;
    const float* x  = xc + (size_t)b * P;
    const float* wi = Wi + (size_t)w * P;
    const float* wf = Wf + (size_t)w * P;
    float ai = 0.f, af = 0.f;
    for (int k = lane * 4; k < P; k += 128) {
        float4 xv  = *(const float4*)(x + k);
        float4 wiv = *(const float4*)(wi + k);
        float4 wfv = *(const float4*)(wf + k);
        ai += xv.x * wiv.x + xv.y * wiv.y + xv.z * wiv.z + xv.w * wiv.w;
        af += xv.x * wfv.x + xv.y * wfv.y + xv.z * wfv.z + xv.w * wfv.w;
    }
    #pragma unroll
    for (int o = 16; o; o >>= 1) {
        ai += __shfl_down_sync(0xffffffffu, ai, o);
        af += __shfl_down_sync(0xffffffffu, af, o);
    }
    if (lane == 0) {
        float i_t = ai + bi[w];
        float f_t = af + bf[w];
        float mp = m_tm1[b * H + w];
        float m = fmaxf(f_t + mp, i_t);
        m_out[b * H + w] = m;
        ie[b * H + w] = expf(i_t - m);
        fe[b * H + w] = expf(f_t - m + mp);
    }
}

// ================= fused state update + readout + groupnorm + gating ========
__global__ __launch_bounds__(128) void state_kernel(
    const float* __restrict__ c_tm1, const float* __restrict__ n_tm1,
    const float* __restrict__ q, const float* __restrict__ k, const float* __restrict__ v,
    const float* __restrict__ o, const float* __restrict__ ie_, const float* __restrict__ fe_,
    const float* __restrict__ skip, const float* __restrict__ r,
    const float* __restrict__ gn_g, const float* __restrict__ gn_b,
    float* __restrict__ c_out, float* __restrict__ n_out, float* __restrict__ y) {
    int bh = blockIdx.x;
    int b = bh >> 3, h = bh & 7;
    __shared__ float qs[D], ks[D], vs[D], hnum[D];
    __shared__ float red[4], rs1[4], rs2[4];
    int tid = threadIdx.x;
    int base = b * HD + h * D;
    qs[tid] = q[base + tid];
    ks[tid] = k[base + tid] * 0.08838834764831845f;   // 1/sqrt(128)
    vs[tid] = v[base + tid];
    float ie = ie_[bh], fe = fe_[bh];
    __syncthreads();

    const float4* crow = (const float4*)(c_tm1 + (size_t)bh * D * D);
    float4* cout = (float4*)(c_out + (size_t)bh * D * D);
    int w = tid >> 5, lane = tid & 31;
    float4 k4 = ((const float4*)ks)[lane];
    float4 q4 = ((const float4*)qs)[lane];
    #pragma unroll 4
    for (int it = 0; it < 32; it++) {
        int d = it * 4 + w;
        float4 c4 = crow[d * 32 + lane];
        float ivd = ie * vs[d];
        float4 cn;
        cn.x = fe * c4.x + ivd * k4.x;
        cn.y = fe * c4.y + ivd * k4.y;
        cn.z = fe * c4.z + ivd * k4.z;
        cn.w = fe * c4.w + ivd * k4.w;
        cout[d * 32 + lane] = cn;
        float part = cn.x * q4.x + cn.y * q4.y + cn.z * q4.z + cn.w * q4.w;
        #pragma unroll
        for (int off = 16; off; off >>= 1) part += __shfl_down_sync(0xffffffffu, part, off);
        if (lane == 0) hnum[d] = part;
    }
    __syncthreads();

    int d = tid;
    float nv = fe * n_tm1[bh * D + d] + ie * ks[d];
    n_out[bh * D + d] = nv;
    float dn = nv * qs[d];
    #pragma unroll
    for (int off = 16; off; off >>= 1) dn += __shfl_down_sync(0xffffffffu, dn, off);
    if (lane == 0) red[w] = dn;
    __syncthreads();
    float denom = fmaxf(red[0] + red[1] + red[2] + red[3], 1.0f);
    float ht = o[base + d] * hnum[d] / denom;

    float s1 = ht, s2 = ht * ht;
    #pragma unroll
    for (int off = 16; off; off >>= 1) {
        s1 += __shfl_down_sync(0xffffffffu, s1, off);
        s2 += __shfl_down_sync(0xffffffffu, s2, off);
    }
    if (lane == 0) { rs1[w] = s1; rs2[w] = s2; }
    __syncthreads();
    float mu  = (rs1[0] + rs1[1] + rs1[2] + rs1[3]) * (1.f / D);
    float var = (rs2[0] + rs2[1] + rs2[2] + rs2[3]) * (1.f / D) - mu * mu;
    float rstd = rsqrtf(var + 1e-5f);
    float xn = (ht - mu) * rstd * gn_g[h * D + d] + gn_b[h * D + d];
    float rv = r[base + d];
    float yv = (xn + skip[base + d]) * (rv / (1.f + expf(-rv)));
    y[base + d] = yv;
}

// ---------------------------------------------------------------------------
extern "C" void kernel_launch(void* const* d_in, const int* in_sizes, int n_in,
                              void* d_out, int out_size) {
    const float* seq    = (const float*)d_in[0];
    const float* c_tm1  = (const float*)d_in[1];
    const float* n_tm1  = (const float*)d_in[2];
    const float* m_tm1  = (const float*)d_in[3];
    const float* ln_g   = (const float*)d_in[4];
    const float* ln_b   = (const float*)d_in[5];
    const float* Wul    = (const float*)d_in[6];
    const float* bul    = (const float*)d_in[7];
    const float* Wur    = (const float*)d_in[8];
    const float* bur    = (const float*)d_in[9];
    const float* conv_w = (const float*)d_in[10];
    const float* conv_b = (const float*)d_in[11];
    const float* Wskip  = (const float*)d_in[12];
    const float* Wi     = (const float*)d_in[13];
    const float* bi     = (const float*)d_in[14];
    const float* Wf     = (const float*)d_in[15];
    const float* bf     = (const float*)d_in[16];
    const float* Wo     = (const float*)d_in[17];
    const float* bo     = (const float*)d_in[18];
    const float* Wq     = (const float*)d_in[19];
    const float* bq     = (const float*)d_in[20];
    const float* Wk     = (const float*)d_in[21];
    const float* bk     = (const float*)d_in[22];
    const float* Wv     = (const float*)d_in[23];
    const float* bv     = (const float*)d_in[24];
    const float* gn_g   = (const float*)d_in[25];
    const float* gn_b   = (const float*)d_in[26];
    const float* Wd     = (const float*)d_in[27];
    const float* bd     = (const float*)d_in[28];

    float* out   = (float*)d_out;                       // [B, DIM]
    float* c_out = out + (size_t)B * DIM;               // [B,H,D,D]
    float* n_out = c_out + (size_t)B * H * D * D;       // [B,H,D]
    float* m_out = n_out + (size_t)B * H * D;           // [B,H]

    float *xn, *xt, *xc, *rt, *qq, *kk, *vv, *oo, *sk, *iee, *fee, *yy;
    cudaGetSymbolAddress((void**)&xn,  g_xn);
    cudaGetSymbolAddress((void**)&xt,  g_xt);
    cudaGetSymbolAddress((void**)&xc,  g_xc);
    cudaGetSymbolAddress((void**)&rt,  g_rt);
    cudaGetSymbolAddress((void**)&qq,  g_q);
    cudaGetSymbolAddress((void**)&kk,  g_k);
    cudaGetSymbolAddress((void**)&vv,  g_v);
    cudaGetSymbolAddress((void**)&oo,  g_o);
    cudaGetSymbolAddress((void**)&sk,  g_sk);
    cudaGetSymbolAddress((void**)&iee, g_ie);
    cudaGetSymbolAddress((void**)&fee, g_fe);
    cudaGetSymbolAddress((void**)&yy,  g_y);

    cudaFuncSetAttribute(gemm_mma, cudaFuncAttributeMaxDynamicSharedMemorySize, GEMM_SMEM);

    // 1. layernorm
    ln_kernel<<<B, 256>>>(seq, ln_g, ln_b, xn);

    // 2+3. x_t = xn@Wul^T+bul [B,P] and r_t = xn@Wur^T+bur [B,HD]
    {
        GemmArgs a{};
        a.d[0] = {xn, Wul, bul, nullptr, xt, P,  DIM, 0};
        a.d[1] = {xn, Wur, bur, nullptr, rt, HD, DIM, 0};
        gemm_mma<<<dim3(P / TILE, B / TILE, 2), 256, GEMM_SMEM>>>(a);
    }

    // 4. causal conv + silu -> x_c
    conv_silu_kernel<<<dim3(P / 256, B), 256>>>(xt, conv_w, conv_b, xc);

    // 5. gates i,f + m_t + exp factors
    if_kernel<<<B, 256>>>(xc, Wi, bi, Wf, bf, m_tm1, m_out, iee, fee);

    // 6. batched 5x GEMM (N=1024, K=2048)
    {
        GemmArgs a{};
        a.d[0] = {xc, Wq,    bq,      nullptr, qq, HD, P, 0};
        a.d[1] = {xc, Wk,    bk,      nullptr, kk, HD, P, 0};
        a.d[2] = {xt, Wv,    bv,      nullptr, vv, HD, P, 0};
        a.d[3] = {xt, Wo,    bo,      nullptr, oo, HD, P, 1};   // sigmoid
        a.d[4] = {xc, Wskip, nullptr, nullptr, sk, HD, P, 0};
        gemm_mma<<<dim3(HD / TILE, B / TILE, 5), 256, GEMM_SMEM>>>(a);
    }

    // 7. fused state update + readout + groupnorm + skip + silu(r) gate
    state_kernel<<<B * H, 128>>>(c_tm1, n_tm1, qq, kk, vv, oo, iee, fee,
                                 sk, rt, gn_g, gn_b, c_out, n_out, yy);

    // 8. out = y @ Wd^T + bd + seq
    {
        GemmArgs a{};
        a.d[0] = {yy, Wd, bd, seq, out, DIM, HD, 0};
        gemm_mma<<<dim3(DIM / TILE, B / TILE, 1), 256, GEMM_SMEM>>>(a);
    }
}